// round 17
// baseline (speedup 1.0000x reference)
#include <cuda_runtime.h>
#include <cuda_fp16.h>
#include <math.h>
#include <stdint.h>
#include <stddef.h>

#define B_   128
#define DIN_ 128
#define T_   1024
#define H_   512
#define G4H_ 2048
#define OUT_ 2

// ---------------- scratch (static device allocations; no cudaMalloc) ----------------
__device__ __half g_xth [(size_t)T_ * B_ * DIN_];  // x transposed, fp16 hi
__device__ __half g_xtl [(size_t)T_ * B_ * DIN_];  // fp16 lo residual
__device__ __half g_wi0 [(size_t)G4H_ * DIN_];     // Wih0 fp16
__device__ __half g_wr0 [(size_t)G4H_ * H_];       // Whh0 fp16
__device__ __half g_wr1 [(size_t)G4H_ * H_];       // Whh1 fp16
__device__ __half g_wi1 [(size_t)G4H_ * H_];       // Wih1 fp16
// h ping-pong buffers: group-blocked, PRE-SWIZZLED (SW128 smem image), aligned for TMA
__device__ __align__(128) __half g_h0a [B_ * H_];
__device__ __align__(128) __half g_h0b [B_ * H_];
__device__ __align__(128) __half g_h1a [B_ * H_];
__device__ __align__(128) __half g_h1b [B_ * H_];
__device__ float g_hA [B_ * H_];                   // final h1 fp32 for fc
__device__ unsigned int g_bar[4 * 32];             // setup barrier
__device__ unsigned int g_flags[4 * 32 * 32];      // per-CTA step flags, 128B stride

// ---------------- small helpers -----------------------------------------------------
__device__ __forceinline__ void hsplit(float v, __half& h, __half& l) {
    h = __float2half(v);
    l = __float2half(v - __half2float(h));
}
__device__ __forceinline__ uint32_t smem_u32(const void* p) {
    uint32_t a;
    asm("{ .reg .u64 t; cvta.to.shared.u64 t, %1; cvt.u32.u64 %0, t; }" : "=r"(a) : "l"(p));
    return a;
}
#define SWZ128(o) ((o) ^ (((o) >> 3) & 0x70))

__device__ __forceinline__ void ldsm_x4(uint32_t* r, uint32_t addr) {
    asm volatile("ldmatrix.sync.aligned.m8n8.x4.shared.b16 {%0,%1,%2,%3}, [%4];"
        : "=r"(r[0]), "=r"(r[1]), "=r"(r[2]), "=r"(r[3]) : "r"(addr));
}
__device__ __forceinline__ void mma16816(float* d, const uint32_t* a, const uint32_t* b) {
    asm volatile("mma.sync.aligned.m16n8k16.row.col.f32.f16.f16.f32 "
        "{%0,%1,%2,%3}, {%4,%5,%6,%7}, {%8,%9}, {%0,%1,%2,%3};"
        : "+f"(d[0]), "+f"(d[1]), "+f"(d[2]), "+f"(d[3])
        : "r"(a[0]), "r"(a[1]), "r"(a[2]), "r"(a[3]), "r"(b[0]), "r"(b[1]));
}
#define CPASYNC16(dst, src) \
    asm volatile("cp.async.cg.shared.global [%0], [%1], 16;" :: "r"(dst), "l"(src))
#define CPCOMMIT() asm volatile("cp.async.commit_group;" ::: "memory")
#define CPWAIT0()  asm volatile("cp.async.wait_group 0;" ::: "memory")

#define MBARRIER_INIT(addr, cnt) \
    asm volatile("mbarrier.init.shared.b64 [%0], %1;" :: "r"(addr), "r"(cnt) : "memory")
#define MBARRIER_EXPECT_TX(addr, tx) \
    asm volatile("mbarrier.arrive.expect_tx.shared.b64 _, [%0], %1;" \
                 :: "r"(addr), "r"(tx) : "memory")
#define TMA_BULK_G2S(dst, src, bytes, mbar) \
    asm volatile("cp.async.bulk.shared::cluster.global.mbarrier::complete_tx::bytes " \
                 "[%0], [%1], %2, [%3];" \
                 :: "r"(dst), "l"(src), "r"(bytes), "r"(mbar) : "memory")
__device__ __forceinline__ void mbar_wait(uint32_t addr, uint32_t parity) {
    uint32_t done = 0;
    while (!done) {
        asm volatile(
            "{\n\t.reg .pred p;\n\t"
            "mbarrier.try_wait.parity.shared.b64 p, [%1], %2, 0x989680;\n\t"
            "selp.b32 %0, 1, 0, p;\n\t}"
            : "=r"(done) : "r"(addr), "r"(parity) : "memory");
    }
}

// ---------------- setup-time barrier (atomic; used once per launch) -------------------
__device__ __forceinline__ void group_barrier(unsigned int* bar) {
    __syncthreads();
    if (threadIdx.x == 0) {
        unsigned int gen;
        asm volatile("ld.acquire.gpu.u32 %0, [%1];" : "=r"(gen) : "l"(bar + 1) : "memory");
        unsigned int arrived;
        asm volatile("atom.add.release.gpu.u32 %0, [%1], 1;"
                     : "=r"(arrived) : "l"(bar) : "memory");
        if (arrived == 31u) {
            asm volatile("st.relaxed.gpu.u32 [%0], 0;" :: "l"(bar) : "memory");
            asm volatile("red.add.release.gpu.u32 [%0], 1;" :: "l"(bar + 1) : "memory");
        } else {
            unsigned int g2;
            do {
                asm volatile("ld.acquire.gpu.u32 %0, [%1];"
                             : "=r"(g2) : "l"(bar + 1) : "memory");
            } while (g2 == gen);
        }
    }
    __syncthreads();
}

// ---------------- transpose x: (B, D, T) -> xt[t][b][d] as fp16 hi/lo ----------------
__global__ void transpose_kernel(const float* __restrict__ x) {
    __shared__ float tile[32][33];
    const int b  = blockIdx.z;
    const int t0 = blockIdx.x * 32;
    const int d0 = blockIdx.y * 32;
    const int tx = threadIdx.x, ty = threadIdx.y;
    #pragma unroll
    for (int i = 0; i < 4; ++i) {
        int d = d0 + ty + i * 8;
        tile[ty + i * 8][tx] = x[((size_t)b * DIN_ + d) * T_ + t0 + tx];
    }
    __syncthreads();
    #pragma unroll
    for (int i = 0; i < 4; ++i) {
        int t = t0 + ty + i * 8;
        float v = tile[tx][ty + i * 8];
        __half h, l;
        hsplit(v, h, l);
        size_t idx = ((size_t)t * B_ + b) * DIN_ + d0 + tx;
        g_xth[idx] = h;
        g_xtl[idx] = l;
    }
}

// ---------------- weight prep -------------------------------------------------------
__global__ void wconv3_kernel(const float* __restrict__ a, __half* __restrict__ oa,
                              const float* __restrict__ b, __half* __restrict__ ob,
                              const float* __restrict__ c, __half* __restrict__ oc,
                              int n) {
    int i = blockIdx.x * blockDim.x + threadIdx.x;
    if (i >= n) return;
    if (blockIdx.y == 0)      oa[i] = __float2half(a[i]);
    else if (blockIdx.y == 1) ob[i] = __float2half(b[i]);
    else                      oc[i] = __float2half(c[i]);
}
__global__ void wconv1_kernel(const float* __restrict__ a, __half* __restrict__ oa,
                              int n) {
    int i = blockIdx.x * blockDim.x + threadIdx.x;
    if (i < n) oa[i] = __float2half(a[i]);
}

// ---------------- fully-fused dual-layer persistent LSTM ------------------------------
// 128 CTAs = 4 b-groups (32 b) x 32 j-tiles (16 j). 256 threads.
// x-MMA for t+1 runs in step t's barrier window (overlapped with the flag poll);
// acc0 lives in persistent registers (xacc) across the window.
#define LSM_W0   0                      // Whh0: 8 chunks x 8192 = 64 KB
#define LSM_W1   65536                  // Whh1: 64 KB
#define LSM_H0   131072                 // h0 tile 32 KB (init: Wih1 temp spans H0+H1)
#define LSM_H1   163840                 // h1 tile 32 KB
#define LSM_RED0 196608                 // 16896 B; doubles as x staging (16384 B)
#define LSM_RED1 213504                 // 16896 B
#define LSM_MBLO 230400                 // mbarrier: lo halves (h0-lo + h1-lo)
#define LSM_MBHI 230416                 // mbarrier: hi halves
#define LSM_TOTAL 230528
// hout staging lives in the dead tail of the H0 tile (safe between last ldsm and next TMA)
#define LSM_HOUT0 (LSM_H0 + 30720)      // 1 KB
#define LSM_HOUT1 (LSM_H0 + 31744)      // 1 KB

__device__ __forceinline__ float tanh_f(float v) {
    float r;
    asm("tanh.approx.f32 %0, %1;" : "=f"(r) : "f"(v));
    return r;
}
__device__ __forceinline__ float sigm_f(float v) {
    return fmaf(tanh_f(v * 0.5f), 0.5f, 0.5f);
}

__global__ void __launch_bounds__(256, 1)
lstm_fused_kernel(const __half* __restrict__ whh0,
                  const __half* __restrict__ whh1,
                  const __half* __restrict__ wih1,
                  const __half* __restrict__ wih0,
                  const float* __restrict__ bih0,
                  const float* __restrict__ bhh0,
                  const float* __restrict__ bih1,
                  const float* __restrict__ bhh1,
                  float* __restrict__ hfin)          // final fp32 h1
{
    extern __shared__ char sm[];
    const uint32_t sb = smem_u32(sm);
    float* red0 = (float*)(sm + LSM_RED0);
    float* red1 = (float*)(sm + LSM_RED1);
    __half* hout0 = (__half*)(sm + LSM_HOUT0);
    __half* hout1 = (__half*)(sm + LSM_HOUT1);
    const uint32_t mbLo = sb + LSM_MBLO;
    const uint32_t mbHi = sb + LSM_MBHI;

    const int tid  = threadIdx.x;
    const int lane = tid & 31;
    const int wid  = tid >> 5;
    const int grp  = blockIdx.x & 3;
    const int jt   = blockIdx.x >> 2;
    const int b0   = grp * 32;
    const int j0   = jt * 16;
    unsigned int* bar    = g_bar + grp * 32;
    unsigned int* myflag = &g_flags[(grp * 32 + jt) * 32];

    const int mf = wid & 3;              // gate
    const int kh = wid >> 5 ? 0 : (wid >> 2);   // (kept simple below)
    const int khx = wid >> 2;            // k-half
    const int a_row = mf * 16 + (lane & 7) + ((lane >> 3) & 1) * 8;
    const int a_kb  = (lane >> 4) * 16;
    const int b_row = (lane & 7) + ((lane >> 4) & 1) * 8;
    const int b_kb  = ((lane >> 3) & 1) * 16;

    // publish addressing constants (pre-swizzled group block)
    const uint32_t cbase = (uint32_t)(j0 >> 6) * 4096;
    const int cc0 = (j0 >> 3) & 7;

    // ---- stage Whh0 -> LSM_W0, Whh1 -> LSM_W1, Wih1 -> temp (LSM_H0+H1, 64 KB) ----
    #pragma unroll
    for (int i = 0; i < 16; ++i) {
        int id = tid + i * 256;           // 0..4095 16B-chunks
        int m  = id >> 6, ch = id & 63;
        int g = m >> 4, jl = m & 15;
        size_t roff = ((size_t)(g * H_ + j0 + jl)) * H_ + ch * 8;
        int c = ch >> 3, cc = ch & 7;
        uint32_t soff = c * 8192 + SWZ128((uint32_t)(m * 128 + cc * 16));
        *(uint4*)(sm + LSM_W0 + soff) = *(const uint4*)(whh0 + roff);
        *(uint4*)(sm + LSM_W1 + soff) = *(const uint4*)(whh1 + roff);
        *(uint4*)(sm + LSM_H0 + soff) = *(const uint4*)(wih1 + roff);
    }

    // ---- zero edge h buffers; reset flag; init mbarriers ----
    if (tid < 64) {
        int bl = tid >> 1, p = tid & 1;
        size_t o = (size_t)(b0 + bl) * H_ + j0 + p * 8;
        *(uint4*)&g_h0b[o] = make_uint4(0, 0, 0, 0);
        *(uint4*)&g_h1b[o] = make_uint4(0, 0, 0, 0);
    }
    if (tid == 0) {
        *myflag = 0;
        MBARRIER_INIT(mbLo, 1u);
        MBARRIER_INIT(mbHi, 1u);
    }
    __syncthreads();

    // ---- Wih1 A-fragments -> registers ----
    uint32_t wi1f[64];
    #pragma unroll
    for (int kf = 0; kf < 16; ++kf) {
        int kfa = khx * 16 + kf;
        int c = kfa >> 2, ks = kfa & 3;
        ldsm_x4(&wi1f[kf * 4],
                sb + LSM_H0 + c * 8192 + SWZ128((uint32_t)(a_row * 128 + ks * 32 + a_kb)));
    }
    __syncthreads();   // wi1f loaded everywhere before H0 overwrite

    // ---- stage Wih0 (64 rows x 128 d fp16, 16 KB) into H0; frags -> registers ----
    #pragma unroll
    for (int i = 0; i < 4; ++i) {
        int id = tid + i * 256;           // 0..1023 16B-chunks
        int m  = id >> 4, ch = id & 15;
        int g = m >> 4, jl = m & 15;
        size_t roff = ((size_t)(g * H_ + j0 + jl)) * DIN_ + ch * 8;
        int c = ch >> 3, cc = ch & 7;
        uint32_t soff = c * 8192 + SWZ128((uint32_t)(m * 128 + cc * 16));
        *(uint4*)(sm + LSM_H0 + soff) = *(const uint4*)(wih0 + roff);
    }
    __syncthreads();
    uint32_t wi0f[16];
    #pragma unroll
    for (int kf = 0; kf < 4; ++kf) {
        int kfa = khx * 4 + kf;
        int c = kfa >> 2, ks = kfa & 3;
        ldsm_x4(&wi0f[kf * 4],
                sb + LSM_H0 + c * 8192 + SWZ128((uint32_t)(a_row * 128 + ks * 32 + a_kb)));
    }

    const int m_lo = lane >> 2;
    float bias0_lo = __ldg(&bih0[mf * H_ + j0 + m_lo])     + __ldg(&bhh0[mf * H_ + j0 + m_lo]);
    float bias0_hi = __ldg(&bih0[mf * H_ + j0 + m_lo + 8]) + __ldg(&bhh0[mf * H_ + j0 + m_lo + 8]);
    float bias1_lo = __ldg(&bih1[mf * H_ + j0 + m_lo])     + __ldg(&bhh1[mf * H_ + j0 + m_lo]);
    float bias1_hi = __ldg(&bih1[mf * H_ + j0 + m_lo + 8]) + __ldg(&bhh1[mf * H_ + j0 + m_lo + 8]);

    group_barrier(bar);   // setup complete

    // x staging into red0 area (hi 8 KB + lo 8 KB), chunked-SW128
    auto stage_x = [&](int tt) {
        #pragma unroll
        for (int i = 0; i < 4; ++i) {
            int id  = tid + i * 256;          // 0..1023
            int hl  = id >> 9;
            int rem = id & 511;
            int bl  = rem >> 4, ch = rem & 15;
            const __half* src = (hl ? g_xtl : g_xth)
                + ((size_t)tt * B_ + b0 + bl) * DIN_ + ch * 8;
            int c = ch >> 3, cc = ch & 7;
            uint32_t dst = sb + LSM_RED0 + hl * 8192 + c * 4096
                         + SWZ128((uint32_t)(bl * 128 + cc * 16));
            CPASYNC16(dst, src);
        }
        CPCOMMIT();
    };

    // persistent layer-0 accumulator: bias -> x-products (window) -> h-products (step)
    float xacc[4][4];
    auto xmma = [&]() {   // xacc = bias0 ; xacc += Wih0 @ (xh + xl)
        #pragma unroll
        for (int nf = 0; nf < 4; ++nf)
            #pragma unroll
            for (int q = 0; q < 4; ++q)
                xacc[nf][q] = (khx == 0) ? ((q & 2) ? bias0_hi : bias0_lo) : 0.f;
        #pragma unroll
        for (int kf = 0; kf < 4; ++kf) {
            int kfa = khx * 4 + kf;
            int c = kfa >> 2, ks = kfa & 3;
            uint32_t xh[8], xl[8];
            #pragma unroll
            for (int nfp = 0; nfp < 2; ++nfp) {
                uint32_t bo = SWZ128((uint32_t)((nfp * 16 + b_row) * 128
                                                 + ks * 32 + b_kb));
                ldsm_x4(xh + nfp * 4, sb + LSM_RED0        + c * 4096 + bo);
                ldsm_x4(xl + nfp * 4, sb + LSM_RED0 + 8192 + c * 4096 + bo);
            }
            #pragma unroll
            for (int nf = 0; nf < 4; ++nf) {
                mma16816(xacc[nf], &wi0f[kf * 4], xh + nf * 2);
                mma16816(xacc[nf], &wi0f[kf * 4], xl + nf * 2);
            }
        }
    };

    // ---- initial: x[0] stage + TMA for t=0; x-MMA(0) ----
    stage_x(0);
    if (tid == 0) {
        const char* s0 = (const char*)(g_h0b + (size_t)b0 * H_);
        const char* s1 = (const char*)(g_h1a + (size_t)b0 * H_);   // t=0 h1 input unused
        MBARRIER_EXPECT_TX(mbLo, 32768u);
        TMA_BULK_G2S(sb + LSM_H0,         s0,         16384u, mbLo);
        TMA_BULK_G2S(sb + LSM_H1,         s1,         16384u, mbLo);
        MBARRIER_EXPECT_TX(mbHi, 32768u);
        TMA_BULK_G2S(sb + LSM_H0 + 16384, s0 + 16384, 16384u, mbHi);
        TMA_BULK_G2S(sb + LSM_H1 + 16384, s1 + 16384, 16384u, mbHi);
    }
    CPWAIT0();
    __syncthreads();
    xmma();

    const int eb = tid & 31;
    const int ej = tid >> 5;
    float c0a = 0.f, c0b = 0.f;   // layer-0 cell states
    float c1a = 0.f, c1b = 0.f;   // layer-1 cell states

    for (int t = 0; t <= T_; ++t) {
        __half* w0 = (t & 1) ? g_h0b : g_h0a;   // h0[t] destination
        __half* w1 = (t & 1) ? g_h1a : g_h1b;   // h1[t-1] destination

        // ---- acc1 init from bias (kh=0 only); acc0 == xacc (bias+x already in) ----
        float acc1[4][4];
        #pragma unroll
        for (int nf = 0; nf < 4; ++nf)
            #pragma unroll
            for (int q = 0; q < 4; ++q)
                acc1[nf][q] = (khx == 0) ? ((q & 2) ? bias1_hi : bias1_lo) : 0.f;

        // ---- wait own h k-half, then main MMA ----
        mbar_wait(khx == 0 ? mbLo : mbHi, (uint32_t)(t & 1));

        #pragma unroll
        for (int kf = 0; kf < 16; ++kf) {
            int kfa = khx * 16 + kf;
            int c = kfa >> 2, ks = kfa & 3;
            uint32_t a0[4], a1[4], b0f[8], b1f[8];
            uint32_t arow = SWZ128((uint32_t)(a_row * 128 + ks * 32 + a_kb));
            ldsm_x4(a0, sb + LSM_W0 + c * 8192 + arow);
            ldsm_x4(a1, sb + LSM_W1 + c * 8192 + arow);
            #pragma unroll
            for (int nfp = 0; nfp < 2; ++nfp) {
                uint32_t bo = SWZ128((uint32_t)((nfp * 16 + b_row) * 128 + ks * 32 + b_kb));
                ldsm_x4(b0f + nfp * 4, sb + LSM_H0 + c * 4096 + bo);
                ldsm_x4(b1f + nfp * 4, sb + LSM_H1 + c * 4096 + bo);
            }
            #pragma unroll
            for (int nf = 0; nf < 4; ++nf) {
                mma16816(xacc[nf], a0, b0f + nf * 2);
                mma16816(acc1[nf], &wi1f[kf * 4], b0f + nf * 2);
                mma16816(acc1[nf], a1, b1f + nf * 2);
            }
        }

        // ---- exchange partials: both layers, ONE sync ----
        #pragma unroll
        for (int nf = 0; nf < 4; ++nf)
            #pragma unroll
            for (int q = 0; q < 4; ++q) {
                int m = (lane >> 2) + 8 * (q >> 1);
                int n = nf * 8 + 2 * (lane & 3) + (q & 1);
                int idx = ((khx * 4 + mf) * 16 + m) * 33 + n;
                red0[idx] = xacc[nf][q];
                red1[idx] = acc1[nf][q];
            }
        __syncthreads();

        // ---- epilogues: compute, gather into smem hout (H0 tail is dead here) ----
        if (t < T_) {
            #pragma unroll
            for (int cell = 0; cell < 2; ++cell) {
                int jl = ej + cell * 8;
                float pre[4];
                #pragma unroll
                for (int g = 0; g < 4; ++g)
                    pre[g] = red0[(g * 16 + jl) * 33 + eb]
                           + red0[((4 + g) * 16 + jl) * 33 + eb];
                float ii = sigm_f(pre[0]), ff = sigm_f(pre[1]);
                float gg = tanh_f(pre[2]), oo = sigm_f(pre[3]);
                float& cc = cell ? c0b : c0a;
                cc = ff * cc + ii * gg;
                hout0[eb * 16 + cell * 8 + ej] = __float2half(oo * tanh_f(cc));
            }
        }
        if (t >= 1) {
            #pragma unroll
            for (int cell = 0; cell < 2; ++cell) {
                int jl = ej + cell * 8;
                float pre[4];
                #pragma unroll
                for (int g = 0; g < 4; ++g)
                    pre[g] = red1[(g * 16 + jl) * 33 + eb]
                           + red1[((4 + g) * 16 + jl) * 33 + eb];
                float ii = sigm_f(pre[0]), ff = sigm_f(pre[1]);
                float gg = tanh_f(pre[2]), oo = sigm_f(pre[3]);
                float& cc = cell ? c1b : c1a;
                cc = ff * cc + ii * gg;
                float hv = oo * tanh_f(cc);
                hout1[eb * 16 + cell * 8 + ej] = __float2half(hv);
                if (t == T_)
                    hfin[(size_t)(b0 + eb) * H_ + j0 + jl] = hv;
            }
        }

        // ---- coalesced publish + barrier window (with overlapped x-MMA for t+1) ----
        if (t < T_) {
            __syncthreads();                       // hout complete
            if (tid < 128) {                       // 16B stores: 128 L2 transactions
                int buf = tid >> 6;
                int idx = tid & 63;
                int ebp = idx >> 1, q = idx & 1;
                if (buf == 0 || t >= 1) {
                    const __half* hsrc = buf ? hout1 : hout0;
                    uint4 v = *(const uint4*)(hsrc + ebp * 16 + q * 8);
                    char* basep = (char*)((buf ? w1 : w0) + (size_t)b0 * H_);
                    uint32_t off = cbase
                        + SWZ128((uint32_t)(ebp * 128 + (cc0 + q) * 16));
                    *(uint4*)(basep + off) = v;
                }
            }
            const unsigned int gen = (unsigned int)(t + 1);
            __syncthreads();                       // STGs ordered before fence
            if (tid == 0) {
                __threadfence();                   // h stores visible gpu-wide
                asm volatile("st.relaxed.gpu.u32 [%0], %1;"
                             :: "l"(myflag), "r"(gen) : "memory");
            }
            // overlapped with flag propagation: stage + x-MMA for t+1
            if (t + 1 < T_) {
                stage_x(t + 1);
                CPWAIT0();
                __syncthreads();                   // x chunks visible CTA-wide
                xmma();
            }
            if (wid == 0) {                        // 32 lanes poll 32 producers
                unsigned int* fp = &g_flags[(grp * 32 + lane) * 32];
                unsigned int v;
                do {
                    asm volatile("ld.acquire.gpu.u32 %0, [%1];"
                                 : "=r"(v) : "l"(fp) : "memory");
                } while (__any_sync(0xffffffffu, v < gen));
                if (lane == 0) {                   // issue next h TMA on detect
                    const char* s0 = (const char*)(w0 + (size_t)b0 * H_);
                    const char* s1 = (const char*)(w1 + (size_t)b0 * H_);
                    MBARRIER_EXPECT_TX(mbLo, 32768u);
                    TMA_BULK_G2S(sb + LSM_H0,         s0,         16384u, mbLo);
                    TMA_BULK_G2S(sb + LSM_H1,         s1,         16384u, mbLo);
                    MBARRIER_EXPECT_TX(mbHi, 32768u);
                    TMA_BULK_G2S(sb + LSM_H0 + 16384, s0 + 16384, 16384u, mbHi);
                    TMA_BULK_G2S(sb + LSM_H1 + 16384, s1 + 16384, 16384u, mbHi);
                }
            }
            __syncthreads();
        }
    }
}

// ---------------- fc head -----------------------------------------------------------
__global__ void fc_kernel(const float* __restrict__ h,
                          const float* __restrict__ W,
                          const float* __restrict__ bias,
                          float* __restrict__ out)
{
    int tid = threadIdx.x;
    int b = tid >> 1, o = tid & 1;
    float s = bias[o];
    const float* hp = h + (size_t)b * H_;
    const float* wp = W + (size_t)o * H_;
    for (int k = 0; k < H_; ++k) s = fmaf(hp[k], wp[k], s);
    out[b * OUT_ + o] = s;
}

// ---------------- launch -------------------------------------------------------------
extern "C" void kernel_launch(void* const* d_in, const int* in_sizes, int n_in,
                              void* d_out, int out_size)
{
    const float* x    = (const float*)d_in[0];
    const float* Wih0 = (const float*)d_in[1];
    const float* Whh0 = (const float*)d_in[2];
    const float* bih0 = (const float*)d_in[3];
    const float* bhh0 = (const float*)d_in[4];
    const float* Wih1 = (const float*)d_in[5];
    const float* Whh1 = (const float*)d_in[6];
    const float* bih1 = (const float*)d_in[7];
    const float* bhh1 = (const float*)d_in[8];
    const float* fcW  = (const float*)d_in[9];
    const float* fcb  = (const float*)d_in[10];
    float* out = (float*)d_out;

    float* hA;
    __half *wi0, *wr0, *wr1, *wi1;
    cudaGetSymbolAddress((void**)&hA,  g_hA);
    cudaGetSymbolAddress((void**)&wi0, g_wi0);
    cudaGetSymbolAddress((void**)&wr0, g_wr0);
    cudaGetSymbolAddress((void**)&wr1, g_wr1);
    cudaGetSymbolAddress((void**)&wi1, g_wi1);

    cudaFuncSetAttribute(lstm_fused_kernel,
                         cudaFuncAttributeMaxDynamicSharedMemorySize, LSM_TOTAL);

    // 1) transpose x -> fp16 hi/lo xt[t][b][d]
    transpose_kernel<<<dim3(T_ / 32, DIN_ / 32, B_), dim3(32, 8)>>>(x);

    // 2) weight prep (all single fp16)
    wconv3_kernel<<<dim3((G4H_ * H_ + 255) / 256, 3), 256>>>(
        Whh0, wr0, Whh1, wr1, Wih1, wi1, G4H_ * H_);
    wconv1_kernel<<<(G4H_ * DIN_ + 255) / 256, 256>>>(Wih0, wi0, G4H_ * DIN_);

    // 3) fully-fused dual-layer recurrence (windowed x-MMA)
    lstm_fused_kernel<<<128, 256, LSM_TOTAL>>>(wr0, wr1, wi1, wi0,
                                               bih0, bhh0, bih1, bhh1, hA);

    // 4) fc head
    fc_kernel<<<1, 256>>>(hA, fcW, fcb, out);
}